// round 16
// baseline (speedup 1.0000x reference)
#include <cuda_runtime.h>
#include <cuda_bf16.h>
#include <mma.h>
#include <cstdint>

using namespace nvcuda;

#define WS 16
#define NH 8
#define CH 96
#define DH 12
#define NTOK 256
#define BATCH 8
#define IMG 256
#define HW (IMG*IMG)
#define NWIN 2048
#define NPIX (BATCH*HW)        // 524288
#define TOTAL (BATCH*CH*HW)    // 50331648
#define EPS 1e-6f
#define BN_EPS 1e-5f
#define QSTR 260               // attn smem row stride (16B-aligned rows)

#define WLDM 104               // bf16 elems per W row (208 B)
#define XLDM 136               // bf16 elems per X row (272 B)

// ---------------- device scratch (allocation-free rule) ---------------------
__device__ float g_qkv[3*CH*NPIX];   // qkv pre-attention  [row 0..287][b][hw]
__device__ float g_out[TOTAL];       // attention output   [b][c][hw]
__device__ float g_y[TOTAL];         // proj output        [b][c][hw]
__device__ float g_sum[CH];
__device__ float g_sq[CH];
__device__ float g_scale[CH];
__device__ float g_shift[CH];
__device__ __nv_bfloat16 g_wHi[4*CH*WLDM];   // slices 0..2 = qkv, 3 = proj
__device__ __nv_bfloat16 g_wLo[4*CH*WLDM];

// ---------------- GEMM smem: X split only ------------------------------------
#define SM_XHI 0
#define SM_XLO (96*XLDM*2)                 // 26112
#define SM_GEMM_TOTAL (2*96*XLDM*2)        // 52224 -> 4 CTAs/SM (208896 B)

// attn smem floats: qkv rows + kv/ksum/vsum + partial buffers (stride 17)
#define ATTN_SMEM_FLOATS (36*QSTR + 144 + 12 + 12 + 144*17 + 12*17 + 12*17)

// ---------------------------------------------------------------------------
__global__ void k_zero() {
    int t = threadIdx.x;
    if (t < CH) { g_sum[t] = 0.f; g_sq[t] = 0.f; }
}

// ---------------------------------------------------------------------------
// K_wsplit: pre-split all weight slices to bf16 hi/lo in global scratch.
// ---------------------------------------------------------------------------
__global__ void k_wsplit(const float* __restrict__ w_qkv, const float* __restrict__ w_proj)
{
    int i = blockIdx.x * 256 + threadIdx.x;          // 4*96*96 = 36864
    if (i >= 4*CH*CH) return;
    int s = i / (CH*CH);
    int r = (i / CH) % CH;
    int c = i % CH;
    float v = (s < 3) ? w_qkv[(size_t)s*CH*CH + r*CH + c] : w_proj[r*CH + c];
    __nv_bfloat16 h = __float2bfloat16(v);
    g_wHi[(size_t)s*CH*WLDM + r*WLDM + c] = h;
    g_wLo[(size_t)s*CH*WLDM + r*WLDM + c] = __float2bfloat16(v - __bfloat162float(h));
}

// ---------------------------------------------------------------------------
// WMMA GEMM (bf16 3-term split, fp32 accum), 4 CTAs/SM, W frags from global L1:
//   per CTA: Y[96, 128tok] = W[96,96] @ X[96,128tok] for nslices W slices.
// ---------------------------------------------------------------------------
__global__ void __launch_bounds__(256, 4)
k_gemm(const float* __restrict__ in, float* __restrict__ outp,
       int nslices, int wbase, int qkv_mode)
{
    extern __shared__ char smem[];
    __nv_bfloat16* xHi = (__nv_bfloat16*)(smem + SM_XHI);
    __nv_bfloat16* xLo = (__nv_bfloat16*)(smem + SM_XLO);

    const int tid = threadIdx.x;
    const int wid = tid >> 5;

    const int b   = blockIdx.x >> 9;       // 512 tiles per batch image
    const int hw0 = (blockIdx.x & 511) << 7;

    // load + split X tile once: [k = channel][n = token]
    {
        const float* xb = in + (size_t)b*CH*HW + hw0;
        for (int i = tid; i < CH*128; i += 256) {
            int k = i >> 7, n = i & 127;
            float v = xb[(size_t)k*HW + n];
            __nv_bfloat16 h = __float2bfloat16(v);
            xHi[k*XLDM + n] = h;
            xLo[k*XLDM + n] = __float2bfloat16(v - __bfloat162float(h));
        }
    }
    __syncthreads();

    const int mrow = wid & 1;    // 0..1 -> M tiles [mrow*3, mrow*3+2]
    const int ncol = wid >> 1;   // 0..3 -> N tiles [ncol*2, ncol*2+1]

    for (int s = 0; s < nslices; s++) {
        const __nv_bfloat16* wHi = g_wHi + (size_t)(wbase + s)*CH*WLDM;
        const __nv_bfloat16* wLo = g_wLo + (size_t)(wbase + s)*CH*WLDM;

        wmma::fragment<wmma::accumulator, 16, 16, 16, float> acc[3][2];
        #pragma unroll
        for (int mt = 0; mt < 3; mt++) {
            wmma::fill_fragment(acc[mt][0], 0.f);
            wmma::fill_fragment(acc[mt][1], 0.f);
        }

        const __nv_bfloat16* aT[3] = { wHi, wHi, wLo };
        const __nv_bfloat16* bT[3] = { xHi, xLo, xHi };

        #pragma unroll 1
        for (int t = 0; t < 3; t++) {
            #pragma unroll 1
            for (int kt = 0; kt < 6; kt++) {
                wmma::fragment<wmma::matrix_b, 16, 16, 16, __nv_bfloat16, wmma::row_major> bf0, bf1;
                wmma::load_matrix_sync(bf0, bT[t] + kt*16*XLDM + (ncol*2)*16,     XLDM);
                wmma::load_matrix_sync(bf1, bT[t] + kt*16*XLDM + (ncol*2 + 1)*16, XLDM);
                #pragma unroll
                for (int mt = 0; mt < 3; mt++) {
                    wmma::fragment<wmma::matrix_a, 16, 16, 16, __nv_bfloat16, wmma::row_major> af;
                    wmma::load_matrix_sync(af, aT[t] + (mrow*3 + mt)*16*WLDM + kt*16, WLDM);
                    wmma::mma_sync(acc[mt][0], af, bf0, acc[mt][0]);
                    wmma::mma_sync(acc[mt][1], af, bf1, acc[mt][1]);
                }
            }
        }

        // store fragments directly to global
        float* out_base;
        unsigned rstride;
        if (qkv_mode) { out_base = outp + (size_t)(s*CH)*NPIX + (size_t)b*HW + hw0; rstride = NPIX; }
        else          { out_base = outp + (size_t)b*CH*HW + hw0;                    rstride = HW;   }

        #pragma unroll
        for (int mt = 0; mt < 3; mt++)
            #pragma unroll
            for (int nt = 0; nt < 2; nt++)
                wmma::store_matrix_sync(out_base + (size_t)(mrow*3 + mt)*16*rstride
                                                 + (ncol*2 + nt)*16,
                                        acc[mt][nt], rstride, wmma::mem_row_major);
    }
}

// ---------------------------------------------------------------------------
// K_attn: one CTA per (window, head). grid (2048, 8).
// kv phase uses (3m x 3c) blocking x 16-way token split -> 3x fewer LDS bytes.
// ---------------------------------------------------------------------------
__global__ void __launch_bounds__(256, 4)
k_attn()
{
    extern __shared__ float smf[];
    float* qkv_s  = smf;                        // 36 x 260
    float* kv_s   = qkv_s + 36*QSTR;            // 144
    float* ksum_s = kv_s + 144;                 // 12
    float* vsum_s = ksum_s + 12;                // 12
    float* pkv    = vsum_s + 12;                // 144 x 17
    float* pks    = pkv + 144*17;               // 12 x 17
    float* pvs    = pks + 12*17;                // 12 x 17

    const int tid = threadIdx.x;
    const int blk = blockIdx.x;
    const int b   = blk >> 8;
    const int wIdx = blk & 255;
    const int h0 = (wIdx >> 4) * WS;
    const int w0 = (wIdx & 15) * WS;
    const int hl = tid >> 4, wl = tid & 15;
    const int pix = (h0 + hl) * IMG + (w0 + wl);
    const int h = blockIdx.y;

    // load 36 qkv rows for this head (float4 over 4-token groups)
    for (int i = tid; i < 36*64; i += 256) {
        int r = i >> 6, g = i & 63;
        int n = g << 2;
        int grow = (r < 12) ? (h*DH + r)
                 : (r < 24) ? (CH + h*DH + (r - 12))
                            : (2*CH + h*DH + (r - 24));
        int p4 = (h0 + (n >> 4)) * IMG + w0 + (n & 15);
        float4 v = *reinterpret_cast<const float4*>(
            g_qkv + (size_t)grow*NPIX + (size_t)b*HW + p4);
        *reinterpret_cast<float4*>(&qkv_s[r*QSTR + n]) = v;
    }
    __syncthreads();

    // l2 norm: q and k normalized IN PLACE (q reloaded in epilogue)
    {
        float t[12]; float s = 0.f;
        #pragma unroll
        for (int m = 0; m < 12; m++) { t[m] = qkv_s[m*QSTR + tid]; s = fmaf(t[m], t[m], s); }
        float r = rsqrtf(s);
        #pragma unroll
        for (int m = 0; m < 12; m++) qkv_s[m*QSTR + tid] = t[m] * r;
    }
    {
        float t[12]; float s = 0.f;
        #pragma unroll
        for (int m = 0; m < 12; m++) { t[m] = qkv_s[(12+m)*QSTR + tid]; s = fmaf(t[m], t[m], s); }
        float r = rsqrtf(s);
        #pragma unroll
        for (int m = 0; m < 12; m++) qkv_s[(12+m)*QSTR + tid] = t[m] * r;
    }
    __syncthreads();

    // kv blocked: thread = (blk16 = (mg,cg), g = token-chunk of 16)
    {
        const int bk = tid & 15;         // block id
        const int g  = tid >> 4;         // 0..15
        const int mg = bk >> 2, cg = bk & 3;
        const int col0 = g * 16;

        float acc[3][3] = {{0.f,0.f,0.f},{0.f,0.f,0.f},{0.f,0.f,0.f}};
        float ks[3] = {0.f,0.f,0.f}, vs[3] = {0.f,0.f,0.f};

        #pragma unroll
        for (int it = 0; it < 4; it++) {
            float4 kk[3], vv[3];
            #pragma unroll
            for (int i = 0; i < 3; i++)
                kk[i] = *reinterpret_cast<const float4*>(&qkv_s[(12 + mg*3 + i)*QSTR + col0 + it*4]);
            #pragma unroll
            for (int j = 0; j < 3; j++)
                vv[j] = *reinterpret_cast<const float4*>(&qkv_s[(24 + cg*3 + j)*QSTR + col0 + it*4]);
            #pragma unroll
            for (int i = 0; i < 3; i++)
                #pragma unroll
                for (int j = 0; j < 3; j++) {
                    acc[i][j] = fmaf(kk[i].x, vv[j].x, acc[i][j]);
                    acc[i][j] = fmaf(kk[i].y, vv[j].y, acc[i][j]);
                    acc[i][j] = fmaf(kk[i].z, vv[j].z, acc[i][j]);
                    acc[i][j] = fmaf(kk[i].w, vv[j].w, acc[i][j]);
                }
            if (cg == 0) {
                #pragma unroll
                for (int i = 0; i < 3; i++)
                    ks[i] += (kk[i].x + kk[i].y) + (kk[i].z + kk[i].w);
            }
            if (mg == 0) {
                #pragma unroll
                for (int j = 0; j < 3; j++)
                    vs[j] += (vv[j].x + vv[j].y) + (vv[j].z + vv[j].w);
            }
        }
        #pragma unroll
        for (int i = 0; i < 3; i++)
            #pragma unroll
            for (int j = 0; j < 3; j++)
                pkv[((mg*3 + i)*12 + cg*3 + j)*17 + g] = acc[i][j];
        if (cg == 0) {
            #pragma unroll
            for (int i = 0; i < 3; i++) pks[(mg*3 + i)*17 + g] = ks[i];
        }
        if (mg == 0) {
            #pragma unroll
            for (int j = 0; j < 3; j++) pvs[(cg*3 + j)*17 + g] = vs[j];
        }
    }
    __syncthreads();

    // fold partials
    if (tid < 144) {
        float s = 0.f;
        #pragma unroll
        for (int u = 0; u < 16; u++) s += pkv[tid*17 + u];
        kv_s[tid] = s;
    } else if (tid < 156) {
        int m = tid - 144;
        float s = 0.f;
        #pragma unroll
        for (int u = 0; u < 16; u++) s += pks[m*17 + u];
        ksum_s[m] = s + EPS;
    } else if (tid < 168) {
        int c2 = tid - 156;
        float s = 0.f;
        #pragma unroll
        for (int u = 0; u < 16; u++) s += pvs[c2*17 + u];
        vsum_s[c2] = s;
    }
    __syncthreads();

    // epilogue: reload normalized q for this token
    float qn[12];
    #pragma unroll
    for (int m = 0; m < 12; m++) qn[m] = qkv_s[m*QSTR + tid];

    float denom = (float)NTOK;
    #pragma unroll
    for (int m = 0; m < 12; m++) denom = fmaf(qn[m], ksum_s[m], denom);
    float tail = 1.0f / denom;

    float* ob = g_out + (size_t)(b*CH + h*DH)*HW + pix;
    #pragma unroll
    for (int c2 = 0; c2 < 12; c2++) {
        float v = vsum_s[c2];
        #pragma unroll
        for (int m = 0; m < 12; m++) v = fmaf(qn[m], kv_s[m*12 + c2], v);
        ob[(size_t)c2*HW] = v * tail;
    }
}

// ---------------------------------------------------------------------------
// K_bnstats: per-channel sum / sumsq over g_y. grid (96, 8).
// ---------------------------------------------------------------------------
__global__ void __launch_bounds__(256)
k_bnstats()
{
    __shared__ float s_s[8], s_q[8];
    const int c = blockIdx.x, b = blockIdx.y;
    const int tid = threadIdx.x;

    const float4* p = reinterpret_cast<const float4*>(g_y + (size_t)(b*CH + c)*HW);
    float s = 0.f, q = 0.f;
    for (int i = tid; i < HW/4; i += 256) {
        float4 v = p[i];
        s += v.x + v.y + v.z + v.w;
        q += v.x*v.x + v.y*v.y + v.z*v.z + v.w*v.w;
    }
    #pragma unroll
    for (int d = 16; d > 0; d >>= 1) {
        s += __shfl_xor_sync(0xffffffffu, s, d);
        q += __shfl_xor_sync(0xffffffffu, q, d);
    }
    if ((tid & 31) == 0) { s_s[tid >> 5] = s; s_q[tid >> 5] = q; }
    __syncthreads();
    if (tid == 0) {
        float ts = 0.f, tq = 0.f;
        #pragma unroll
        for (int i = 0; i < 8; i++) { ts += s_s[i]; tq += s_q[i]; }
        atomicAdd(&g_sum[c], ts);
        atomicAdd(&g_sq[c],  tq);
    }
}

// ---------------------------------------------------------------------------
__global__ void k_bnprep(const float* __restrict__ gamma, const float* __restrict__ beta)
{
    int c = threadIdx.x;
    if (c < CH) {
        const float inv_n = 1.0f / (float)NPIX;
        float mean = g_sum[c] * inv_n;
        float var  = fmaf(-mean, mean, g_sq[c] * inv_n);
        float rstd = rsqrtf(var + BN_EPS);
        float sc = rstd * gamma[c];
        g_scale[c] = sc;
        g_shift[c] = fmaf(-mean, sc, beta[c]);
    }
}

__global__ void __launch_bounds__(256)
k_bnapply(float* __restrict__ out)
{
    int i = blockIdx.x * 256 + threadIdx.x;
    int c = (i >> 14) % CH;
    float sc = g_scale[c], sh = g_shift[c];
    float4 v = reinterpret_cast<const float4*>(g_y)[i];
    v.x = fmaf(v.x, sc, sh);
    v.y = fmaf(v.y, sc, sh);
    v.z = fmaf(v.z, sc, sh);
    v.w = fmaf(v.w, sc, sh);
    reinterpret_cast<float4*>(out)[i] = v;
}

// ---------------------------------------------------------------------------
extern "C" void kernel_launch(void* const* d_in, const int* in_sizes, int n_in,
                              void* d_out, int out_size)
{
    const float* x      = (const float*)d_in[0];
    const float* w_qkv  = (const float*)d_in[1];
    const float* w_proj = (const float*)d_in[2];
    const float* gamma  = (const float*)d_in[3];
    const float* beta   = (const float*)d_in[4];

    const int smem_attn = ATTN_SMEM_FLOATS * (int)sizeof(float);
    cudaFuncSetAttribute(k_gemm, cudaFuncAttributeMaxDynamicSharedMemorySize, SM_GEMM_TOTAL);
    cudaFuncSetAttribute(k_attn, cudaFuncAttributeMaxDynamicSharedMemorySize, smem_attn);

    float* gqkv;  cudaGetSymbolAddress((void**)&gqkv, g_qkv);
    float* gout;  cudaGetSymbolAddress((void**)&gout, g_out);
    float* gy;    cudaGetSymbolAddress((void**)&gy,   g_y);

    k_zero<<<1, 128>>>();
    k_wsplit<<<144, 256>>>(w_qkv, w_proj);
    k_gemm<<<4096, 256, SM_GEMM_TOTAL>>>(x, gqkv, 3, 0, 1);
    k_attn<<<dim3(NWIN, NH), 256, smem_attn>>>();
    k_gemm<<<4096, 256, SM_GEMM_TOTAL>>>(gout, gy, 1, 3, 0);
    k_bnstats<<<dim3(CH, BATCH), 256>>>();
    k_bnprep<<<1, 128>>>(gamma, beta);
    k_bnapply<<<TOTAL/4/256, 256>>>((float*)d_out);
}

// round 17
// speedup vs baseline: 1.9679x; 1.9679x over previous
#include <cuda_runtime.h>
#include <cuda_bf16.h>
#include <mma.h>
#include <cstdint>

using namespace nvcuda;

#define WS 16
#define NH 8
#define CH 96
#define DH 12
#define NTOK 256
#define BATCH 8
#define IMG 256
#define HW (IMG*IMG)
#define NWIN 2048
#define NPIX (BATCH*HW)        // 524288
#define TOTAL (BATCH*CH*HW)    // 50331648
#define EPS 1e-6f
#define BN_EPS 1e-5f
#define QSTR 260               // attn smem row stride (16B-aligned rows)

#define WLDM 104               // bf16 elems per W row (208 B)
#define XLDM 136               // bf16 elems per X row (272 B)

// ---------------- device scratch (allocation-free rule) ---------------------
__device__ float g_qkv[3*CH*NPIX];   // qkv pre-attention  [row 0..287][b][hw]
__device__ float g_out[TOTAL];       // attention output   [b][c][hw]
__device__ float g_y[TOTAL];         // proj output        [b][c][hw]
__device__ float g_sum[CH];
__device__ float g_sq[CH];
__device__ float g_scale[CH];
__device__ float g_shift[CH];
__device__ __nv_bfloat16 g_wHi[4*CH*WLDM];   // slices 0..2 = qkv, 3 = proj
__device__ __nv_bfloat16 g_wLo[4*CH*WLDM];

// ---------------- GEMM smem: X split only ------------------------------------
#define SM_XHI 0
#define SM_XLO (96*XLDM*2)                 // 26112
#define SM_GEMM_TOTAL (2*96*XLDM*2)        // 52224 -> 3 CTAs/SM

// attn smem floats: qkv rows + kv/ksum/vsum + partial buffers (stride 17)
#define ATTN_SMEM_FLOATS (36*QSTR + 144 + 12 + 12 + 144*17 + 12*17 + 12*17)

// ---------------------------------------------------------------------------
__global__ void k_zero() {
    int t = threadIdx.x;
    if (t < CH) { g_sum[t] = 0.f; g_sq[t] = 0.f; }
}

// ---------------------------------------------------------------------------
// K_wsplit: pre-split all weight slices to bf16 hi/lo in global scratch.
// ---------------------------------------------------------------------------
__global__ void k_wsplit(const float* __restrict__ w_qkv, const float* __restrict__ w_proj)
{
    int i = blockIdx.x * 256 + threadIdx.x;          // 4*96*96 = 36864
    if (i >= 4*CH*CH) return;
    int s = i / (CH*CH);
    int r = (i / CH) % CH;
    int c = i % CH;
    float v = (s < 3) ? w_qkv[(size_t)s*CH*CH + r*CH + c] : w_proj[r*CH + c];
    __nv_bfloat16 h = __float2bfloat16(v);
    g_wHi[(size_t)s*CH*WLDM + r*WLDM + c] = h;
    g_wLo[(size_t)s*CH*WLDM + r*WLDM + c] = __float2bfloat16(v - __bfloat162float(h));
}

// ---------------------------------------------------------------------------
// WMMA GEMM (bf16 3-term split, fp32 accum), 3 CTAs/SM, W frags from global L1:
//   per CTA: Y[96, 128tok] = W[96,96] @ X[96,128tok] for nslices W slices.
// ---------------------------------------------------------------------------
__global__ void __launch_bounds__(256, 3)
k_gemm(const float* __restrict__ in, float* __restrict__ outp,
       int nslices, int wbase, int qkv_mode)
{
    extern __shared__ char smem[];
    __nv_bfloat16* xHi = (__nv_bfloat16*)(smem + SM_XHI);
    __nv_bfloat16* xLo = (__nv_bfloat16*)(smem + SM_XLO);

    const int tid = threadIdx.x;
    const int wid = tid >> 5;

    const int b   = blockIdx.x >> 9;       // 512 tiles per batch image
    const int hw0 = (blockIdx.x & 511) << 7;

    // load + split X tile once: [k = channel][n = token]
    {
        const float* xb = in + (size_t)b*CH*HW + hw0;
        for (int i = tid; i < CH*128; i += 256) {
            int k = i >> 7, n = i & 127;
            float v = xb[(size_t)k*HW + n];
            __nv_bfloat16 h = __float2bfloat16(v);
            xHi[k*XLDM + n] = h;
            xLo[k*XLDM + n] = __float2bfloat16(v - __bfloat162float(h));
        }
    }
    __syncthreads();

    const int mrow = wid & 1;    // 0..1 -> M tiles [mrow*3, mrow*3+2]
    const int ncol = wid >> 1;   // 0..3 -> N tiles [ncol*2, ncol*2+1]

    for (int s = 0; s < nslices; s++) {
        const __nv_bfloat16* wHi = g_wHi + (size_t)(wbase + s)*CH*WLDM;
        const __nv_bfloat16* wLo = g_wLo + (size_t)(wbase + s)*CH*WLDM;

        wmma::fragment<wmma::accumulator, 16, 16, 16, float> acc[3][2];
        #pragma unroll
        for (int mt = 0; mt < 3; mt++) {
            wmma::fill_fragment(acc[mt][0], 0.f);
            wmma::fill_fragment(acc[mt][1], 0.f);
        }

        const __nv_bfloat16* aT[3] = { wHi, wHi, wLo };
        const __nv_bfloat16* bT[3] = { xHi, xLo, xHi };

        #pragma unroll 1
        for (int t = 0; t < 3; t++) {
            #pragma unroll 1
            for (int kt = 0; kt < 6; kt++) {
                wmma::fragment<wmma::matrix_b, 16, 16, 16, __nv_bfloat16, wmma::row_major> bf0, bf1;
                wmma::load_matrix_sync(bf0, bT[t] + kt*16*XLDM + (ncol*2)*16,     XLDM);
                wmma::load_matrix_sync(bf1, bT[t] + kt*16*XLDM + (ncol*2 + 1)*16, XLDM);
                #pragma unroll
                for (int mt = 0; mt < 3; mt++) {
                    wmma::fragment<wmma::matrix_a, 16, 16, 16, __nv_bfloat16, wmma::row_major> af;
                    wmma::load_matrix_sync(af, aT[t] + (mrow*3 + mt)*16*WLDM + kt*16, WLDM);
                    wmma::mma_sync(acc[mt][0], af, bf0, acc[mt][0]);
                    wmma::mma_sync(acc[mt][1], af, bf1, acc[mt][1]);
                }
            }
        }

        // store fragments directly to global
        float* out_base;
        unsigned rstride;
        if (qkv_mode) { out_base = outp + (size_t)(s*CH)*NPIX + (size_t)b*HW + hw0; rstride = NPIX; }
        else          { out_base = outp + (size_t)b*CH*HW + hw0;                    rstride = HW;   }

        #pragma unroll
        for (int mt = 0; mt < 3; mt++)
            #pragma unroll
            for (int nt = 0; nt < 2; nt++)
                wmma::store_matrix_sync(out_base + (size_t)(mrow*3 + mt)*16*rstride
                                                 + (ncol*2 + nt)*16,
                                        acc[mt][nt], rstride, wmma::mem_row_major);
    }
}

// ---------------------------------------------------------------------------
// K_attn: one CTA per (window, head). grid (2048, 8).
// kv phase uses (3m x 3c) blocking x 16-way token split -> 3x fewer LDS bytes.
// ---------------------------------------------------------------------------
__global__ void __launch_bounds__(256, 4)
k_attn()
{
    extern __shared__ float smf[];
    float* qkv_s  = smf;                        // 36 x 260
    float* kv_s   = qkv_s + 36*QSTR;            // 144
    float* ksum_s = kv_s + 144;                 // 12
    float* vsum_s = ksum_s + 12;                // 12
    float* pkv    = vsum_s + 12;                // 144 x 17
    float* pks    = pkv + 144*17;               // 12 x 17
    float* pvs    = pks + 12*17;                // 12 x 17

    const int tid = threadIdx.x;
    const int blk = blockIdx.x;
    const int b   = blk >> 8;
    const int wIdx = blk & 255;
    const int h0 = (wIdx >> 4) * WS;
    const int w0 = (wIdx & 15) * WS;
    const int hl = tid >> 4, wl = tid & 15;
    const int pix = (h0 + hl) * IMG + (w0 + wl);
    const int h = blockIdx.y;

    // load 36 qkv rows for this head (float4 over 4-token groups)
    for (int i = tid; i < 36*64; i += 256) {
        int r = i >> 6, g = i & 63;
        int n = g << 2;
        int grow = (r < 12) ? (h*DH + r)
                 : (r < 24) ? (CH + h*DH + (r - 12))
                            : (2*CH + h*DH + (r - 24));
        int p4 = (h0 + (n >> 4)) * IMG + w0 + (n & 15);
        float4 v = *reinterpret_cast<const float4*>(
            g_qkv + (size_t)grow*NPIX + (size_t)b*HW + p4);
        *reinterpret_cast<float4*>(&qkv_s[r*QSTR + n]) = v;
    }
    __syncthreads();

    // l2 norm: q and k normalized IN PLACE (q reloaded in epilogue)
    {
        float t[12]; float s = 0.f;
        #pragma unroll
        for (int m = 0; m < 12; m++) { t[m] = qkv_s[m*QSTR + tid]; s = fmaf(t[m], t[m], s); }
        float r = rsqrtf(s);
        #pragma unroll
        for (int m = 0; m < 12; m++) qkv_s[m*QSTR + tid] = t[m] * r;
    }
    {
        float t[12]; float s = 0.f;
        #pragma unroll
        for (int m = 0; m < 12; m++) { t[m] = qkv_s[(12+m)*QSTR + tid]; s = fmaf(t[m], t[m], s); }
        float r = rsqrtf(s);
        #pragma unroll
        for (int m = 0; m < 12; m++) qkv_s[(12+m)*QSTR + tid] = t[m] * r;
    }
    __syncthreads();

    // kv blocked: thread = (blk16 = (mg,cg), g = token-chunk of 16)
    {
        const int bk = tid & 15;         // block id
        const int g  = tid >> 4;         // 0..15
        const int mg = bk >> 2, cg = bk & 3;
        const int col0 = g * 16;

        float acc[3][3] = {{0.f,0.f,0.f},{0.f,0.f,0.f},{0.f,0.f,0.f}};
        float ks[3] = {0.f,0.f,0.f}, vs[3] = {0.f,0.f,0.f};

        #pragma unroll
        for (int it = 0; it < 4; it++) {
            float4 kk[3], vv[3];
            #pragma unroll
            for (int i = 0; i < 3; i++)
                kk[i] = *reinterpret_cast<const float4*>(&qkv_s[(12 + mg*3 + i)*QSTR + col0 + it*4]);
            #pragma unroll
            for (int j = 0; j < 3; j++)
                vv[j] = *reinterpret_cast<const float4*>(&qkv_s[(24 + cg*3 + j)*QSTR + col0 + it*4]);
            #pragma unroll
            for (int i = 0; i < 3; i++)
                #pragma unroll
                for (int j = 0; j < 3; j++) {
                    acc[i][j] = fmaf(kk[i].x, vv[j].x, acc[i][j]);
                    acc[i][j] = fmaf(kk[i].y, vv[j].y, acc[i][j]);
                    acc[i][j] = fmaf(kk[i].z, vv[j].z, acc[i][j]);
                    acc[i][j] = fmaf(kk[i].w, vv[j].w, acc[i][j]);
                }
            if (cg == 0) {
                #pragma unroll
                for (int i = 0; i < 3; i++)
                    ks[i] += (kk[i].x + kk[i].y) + (kk[i].z + kk[i].w);
            }
            if (mg == 0) {
                #pragma unroll
                for (int j = 0; j < 3; j++)
                    vs[j] += (vv[j].x + vv[j].y) + (vv[j].z + vv[j].w);
            }
        }
        #pragma unroll
        for (int i = 0; i < 3; i++)
            #pragma unroll
            for (int j = 0; j < 3; j++)
                pkv[((mg*3 + i)*12 + cg*3 + j)*17 + g] = acc[i][j];
        if (cg == 0) {
            #pragma unroll
            for (int i = 0; i < 3; i++) pks[(mg*3 + i)*17 + g] = ks[i];
        }
        if (mg == 0) {
            #pragma unroll
            for (int j = 0; j < 3; j++) pvs[(cg*3 + j)*17 + g] = vs[j];
        }
    }
    __syncthreads();

    // fold partials
    if (tid < 144) {
        float s = 0.f;
        #pragma unroll
        for (int u = 0; u < 16; u++) s += pkv[tid*17 + u];
        kv_s[tid] = s;
    } else if (tid < 156) {
        int m = tid - 144;
        float s = 0.f;
        #pragma unroll
        for (int u = 0; u < 16; u++) s += pks[m*17 + u];
        ksum_s[m] = s + EPS;
    } else if (tid < 168) {
        int c2 = tid - 156;
        float s = 0.f;
        #pragma unroll
        for (int u = 0; u < 16; u++) s += pvs[c2*17 + u];
        vsum_s[c2] = s;
    }
    __syncthreads();

    // epilogue: reload normalized q for this token
    float qn[12];
    #pragma unroll
    for (int m = 0; m < 12; m++) qn[m] = qkv_s[m*QSTR + tid];

    float denom = (float)NTOK;
    #pragma unroll
    for (int m = 0; m < 12; m++) denom = fmaf(qn[m], ksum_s[m], denom);
    float tail = 1.0f / denom;

    float* ob = g_out + (size_t)(b*CH + h*DH)*HW + pix;
    #pragma unroll
    for (int c2 = 0; c2 < 12; c2++) {
        float v = vsum_s[c2];
        #pragma unroll
        for (int m = 0; m < 12; m++) v = fmaf(qn[m], kv_s[m*12 + c2], v);
        ob[(size_t)c2*HW] = v * tail;
    }
}

// ---------------------------------------------------------------------------
// K_bnstats: per-channel sum / sumsq over g_y. grid (96, 8).
// ---------------------------------------------------------------------------
__global__ void __launch_bounds__(256)
k_bnstats()
{
    __shared__ float s_s[8], s_q[8];
    const int c = blockIdx.x, b = blockIdx.y;
    const int tid = threadIdx.x;

    const float4* p = reinterpret_cast<const float4*>(g_y + (size_t)(b*CH + c)*HW);
    float s = 0.f, q = 0.f;
    for (int i = tid; i < HW/4; i += 256) {
        float4 v = p[i];
        s += v.x + v.y + v.z + v.w;
        q += v.x*v.x + v.y*v.y + v.z*v.z + v.w*v.w;
    }
    #pragma unroll
    for (int d = 16; d > 0; d >>= 1) {
        s += __shfl_xor_sync(0xffffffffu, s, d);
        q += __shfl_xor_sync(0xffffffffu, q, d);
    }
    if ((tid & 31) == 0) { s_s[tid >> 5] = s; s_q[tid >> 5] = q; }
    __syncthreads();
    if (tid == 0) {
        float ts = 0.f, tq = 0.f;
        #pragma unroll
        for (int i = 0; i < 8; i++) { ts += s_s[i]; tq += s_q[i]; }
        atomicAdd(&g_sum[c], ts);
        atomicAdd(&g_sq[c],  tq);
    }
}

// ---------------------------------------------------------------------------
__global__ void k_bnprep(const float* __restrict__ gamma, const float* __restrict__ beta)
{
    int c = threadIdx.x;
    if (c < CH) {
        const float inv_n = 1.0f / (float)NPIX;
        float mean = g_sum[c] * inv_n;
        float var  = fmaf(-mean, mean, g_sq[c] * inv_n);
        float rstd = rsqrtf(var + BN_EPS);
        float sc = rstd * gamma[c];
        g_scale[c] = sc;
        g_shift[c] = fmaf(-mean, sc, beta[c]);
    }
}

__global__ void __launch_bounds__(256)
k_bnapply(float* __restrict__ out)
{
    int i = blockIdx.x * 256 + threadIdx.x;
    int c = (i >> 14) % CH;
    float sc = g_scale[c], sh = g_shift[c];
    float4 v = reinterpret_cast<const float4*>(g_y)[i];
    v.x = fmaf(v.x, sc, sh);
    v.y = fmaf(v.y, sc, sh);
    v.z = fmaf(v.z, sc, sh);
    v.w = fmaf(v.w, sc, sh);
    reinterpret_cast<float4*>(out)[i] = v;
}

// ---------------------------------------------------------------------------
extern "C" void kernel_launch(void* const* d_in, const int* in_sizes, int n_in,
                              void* d_out, int out_size)
{
    const float* x      = (const float*)d_in[0];
    const float* w_qkv  = (const float*)d_in[1];
    const float* w_proj = (const float*)d_in[2];
    const float* gamma  = (const float*)d_in[3];
    const float* beta   = (const float*)d_in[4];

    const int smem_attn = ATTN_SMEM_FLOATS * (int)sizeof(float);
    cudaFuncSetAttribute(k_gemm, cudaFuncAttributeMaxDynamicSharedMemorySize, SM_GEMM_TOTAL);
    cudaFuncSetAttribute(k_attn, cudaFuncAttributeMaxDynamicSharedMemorySize, smem_attn);

    float* gqkv;  cudaGetSymbolAddress((void**)&gqkv, g_qkv);
    float* gout;  cudaGetSymbolAddress((void**)&gout, g_out);
    float* gy;    cudaGetSymbolAddress((void**)&gy,   g_y);

    k_zero<<<1, 128>>>();
    k_wsplit<<<144, 256>>>(w_qkv, w_proj);
    k_gemm<<<4096, 256, SM_GEMM_TOTAL>>>(x, gqkv, 3, 0, 1);
    k_attn<<<dim3(NWIN, NH), 256, smem_attn>>>();
    k_gemm<<<4096, 256, SM_GEMM_TOTAL>>>(gout, gy, 1, 3, 0);
    k_bnstats<<<dim3(CH, BATCH), 256>>>();
    k_bnprep<<<1, 128>>>(gamma, beta);
    k_bnapply<<<TOTAL/4/256, 256>>>((float*)d_out);
}